// round 1
// baseline (speedup 1.0000x reference)
#include <cuda_runtime.h>

// Problem constants
namespace {
constexpr int B_    = 16;
constexpr int N_    = 2048;
constexpr int H_    = 256;
constexpr int KOUT_ = 128;
constexpr int NB_   = 4;
constexpr int NG_   = 2;
constexpr float NEG_ = 0.01f;

constexpr int TI = 128;   // i-tile (rows)
constexpr int TH = 128;   // h-tile (cols)
constexpr int TJ = 32;    // k-tile
constexpr int NTILES = N_ / TI;  // 16
}

// Scratch (allocation-free: device globals)
__device__ float g_h1[(size_t)B_ * N_ * H_];
__device__ float g_h2[(size_t)B_ * N_ * H_];
__device__ float g_part[(size_t)B_ * NTILES * KOUT_ * 3];

__device__ __forceinline__ float fsqrt_fast(float v) {
    float r;
    asm("sqrt.approx.f32 %0, %1;" : "=f"(r) : "f"(v));
    return r;
}
__device__ __forceinline__ float lrelu(float v) { return v > 0.f ? v : NEG_ * v; }

// ---------------------------------------------------------------------------
// Stage 1: h1[b,i,h] = leaky( u·W1[0:2] + |x_i|·W1[2] + proj·W1[3:7]
//                             + sum_j sqrt(x_i·x_j) · W1[7+j] + b1 )
// Fused: D tile computed on the fly in SMEM (never materialize [N,N] dots).
// Grid: (N/TI, H/TH, B), 256 threads, 8x8 microtile per thread.
// ---------------------------------------------------------------------------
__global__ __launch_bounds__(256, 2)
void k_stage1(const float* __restrict__ x, const float* __restrict__ u,
              const float* __restrict__ basis, const float* __restrict__ W1,
              const float* __restrict__ b1) {
    const int i0 = blockIdx.x * TI;
    const int h0 = blockIdx.y * TH;
    const int b  = blockIdx.z;

    __shared__ float s_xi[TI][4];
    __shared__ float s_xj[TJ][4];
    __shared__ float s_Dt[TJ][TI + 4];   // D transposed: [k][i], padded
    __shared__ float s_Wt[TJ][TH];
    __shared__ float s_norm[TI];
    __shared__ float s_proj[TI][NB_];

    const int t  = threadIdx.x;
    const int tx = t & 15;
    const int ty = t >> 4;

    const float* xb = x + (size_t)b * N_ * 3;

    // Per-row scalars (norms, basis projections)
    if (t < TI) {
        float x0 = xb[(i0 + t) * 3 + 0];
        float x1 = xb[(i0 + t) * 3 + 1];
        float x2 = xb[(i0 + t) * 3 + 2];
        s_xi[t][0] = x0; s_xi[t][1] = x1; s_xi[t][2] = x2;
        s_norm[t] = fsqrt_fast(x0 * x0 + x1 * x1 + x2 * x2);
#pragma unroll
        for (int k = 0; k < NB_; k++) {
            const float* bk = basis + ((size_t)b * NB_ + k) * 3;
            s_proj[t][k] = x0 * bk[0] + x1 * bk[1] + x2 * bk[2];
        }
    }
    __syncthreads();

    // Init accumulators with the "small" scalar terms + bias
    float acc[8][8];
    {
        const float u0 = u[b * NG_ + 0];
        const float u1 = u[b * NG_ + 1];
        float baseh[8], wn[8], wp[NB_][8];
#pragma unroll
        for (int c = 0; c < 8; c++) {
            int h = h0 + tx * 8 + c;
            baseh[c] = b1[h] + u0 * W1[0 * H_ + h] + u1 * W1[1 * H_ + h];
            wn[c] = W1[2 * H_ + h];
#pragma unroll
            for (int k = 0; k < NB_; k++) wp[k][c] = W1[(3 + k) * H_ + h];
        }
#pragma unroll
        for (int r = 0; r < 8; r++) {
            int il = ty * 8 + r;
            float nrm = s_norm[il];
            float p0 = s_proj[il][0], p1 = s_proj[il][1];
            float p2 = s_proj[il][2], p3 = s_proj[il][3];
#pragma unroll
            for (int c = 0; c < 8; c++) {
                acc[r][c] = baseh[c] + nrm * wn[c]
                          + p0 * wp[0][c] + p1 * wp[1][c]
                          + p2 * wp[2][c] + p3 * wp[3][c];
            }
        }
    }

    const float* W1d = W1 + 7 * H_;  // dots block of W1

    for (int j0 = 0; j0 < N_; j0 += TJ) {
        __syncthreads();  // previous GEMM done before overwriting tiles
        if (t < TJ) {
            s_xj[t][0] = xb[(j0 + t) * 3 + 0];
            s_xj[t][1] = xb[(j0 + t) * 3 + 1];
            s_xj[t][2] = xb[(j0 + t) * 3 + 2];
        }
#pragma unroll
        for (int v = 0; v < 4; v++) {
            int idx = t + v * 256;          // float4 id, 0..1023
            int r   = idx >> 5;             // row 0..31
            int c4  = idx & 31;             // col/4
            *(float4*)&s_Wt[r][c4 * 4] =
                *(const float4*)&W1d[(size_t)(j0 + r) * H_ + h0 + c4 * 4];
        }
        __syncthreads();

        // D tile: Dt[k][i] = sqrt(x_{i0+i} . x_{j0+k})
        {
            int k  = t & 31;
            int ib = (t >> 5) * 16;
            float a0 = s_xj[k][0], a1 = s_xj[k][1], a2 = s_xj[k][2];
#pragma unroll
            for (int ii = 0; ii < 16; ii++) {
                int i = ib + ii;
                float d = a0 * s_xi[i][0] + a1 * s_xi[i][1] + a2 * s_xi[i][2];
                s_Dt[k][i] = fsqrt_fast(d);
            }
        }
        __syncthreads();

#pragma unroll
        for (int k = 0; k < TJ; k++) {
            float a[8], w[8];
            *(float4*)&a[0] = *(const float4*)&s_Dt[k][ty * 8];
            *(float4*)&a[4] = *(const float4*)&s_Dt[k][ty * 8 + 4];
            *(float4*)&w[0] = *(const float4*)&s_Wt[k][tx * 8];
            *(float4*)&w[4] = *(const float4*)&s_Wt[k][tx * 8 + 4];
#pragma unroll
            for (int r = 0; r < 8; r++)
#pragma unroll
                for (int c = 0; c < 8; c++)
                    acc[r][c] = fmaf(a[r], w[c], acc[r][c]);
        }
    }

    // Epilogue: LeakyReLU, store h1
    float* outp = g_h1 + ((size_t)b * N_ + i0 + ty * 8) * H_ + h0 + tx * 8;
#pragma unroll
    for (int r = 0; r < 8; r++) {
        float4 v0, v1;
        v0.x = lrelu(acc[r][0]); v0.y = lrelu(acc[r][1]);
        v0.z = lrelu(acc[r][2]); v0.w = lrelu(acc[r][3]);
        v1.x = lrelu(acc[r][4]); v1.y = lrelu(acc[r][5]);
        v1.z = lrelu(acc[r][6]); v1.w = lrelu(acc[r][7]);
        *(float4*)(outp + (size_t)r * H_)     = v0;
        *(float4*)(outp + (size_t)r * H_ + 4) = v1;
    }
}

// ---------------------------------------------------------------------------
// Stage 2: h2 = leaky(h1 @ W2 + b2).  A: [B*N, 256] row-major.
// ---------------------------------------------------------------------------
__global__ __launch_bounds__(256, 2)
void k_stage2(const float* __restrict__ W2, const float* __restrict__ b2) {
    const int row0 = blockIdx.x * TI;
    const int h0   = blockIdx.y * TH;

    __shared__ float s_At[TJ][TI + 4];
    __shared__ float s_Wt[TJ][TH];

    const int t  = threadIdx.x;
    const int tx = t & 15;
    const int ty = t >> 4;

    float acc[8][8];
    {
        float bc[8];
#pragma unroll
        for (int c = 0; c < 8; c++) bc[c] = b2[h0 + tx * 8 + c];
#pragma unroll
        for (int r = 0; r < 8; r++)
#pragma unroll
            for (int c = 0; c < 8; c++) acc[r][c] = bc[c];
    }

    for (int k0 = 0; k0 < H_; k0 += TJ) {
        __syncthreads();
#pragma unroll
        for (int v = 0; v < 4; v++) {
            int idx = t + v * 256;          // float4 id, 0..1023
            int i   = idx >> 3;             // row 0..127
            int c4  = idx & 7;
            float4 w = *(const float4*)&g_h1[(size_t)(row0 + i) * H_ + k0 + c4 * 4];
            s_At[c4 * 4 + 0][i] = w.x;
            s_At[c4 * 4 + 1][i] = w.y;
            s_At[c4 * 4 + 2][i] = w.z;
            s_At[c4 * 4 + 3][i] = w.w;
        }
#pragma unroll
        for (int v = 0; v < 4; v++) {
            int idx = t + v * 256;
            int r   = idx >> 5;
            int c4  = idx & 31;
            *(float4*)&s_Wt[r][c4 * 4] =
                *(const float4*)&W2[(size_t)(k0 + r) * H_ + h0 + c4 * 4];
        }
        __syncthreads();
#pragma unroll
        for (int k = 0; k < TJ; k++) {
            float a[8], w[8];
            *(float4*)&a[0] = *(const float4*)&s_At[k][ty * 8];
            *(float4*)&a[4] = *(const float4*)&s_At[k][ty * 8 + 4];
            *(float4*)&w[0] = *(const float4*)&s_Wt[k][tx * 8];
            *(float4*)&w[4] = *(const float4*)&s_Wt[k][tx * 8 + 4];
#pragma unroll
            for (int r = 0; r < 8; r++)
#pragma unroll
                for (int c = 0; c < 8; c++)
                    acc[r][c] = fmaf(a[r], w[c], acc[r][c]);
        }
    }

    float* outp = g_h2 + ((size_t)row0 + ty * 8) * H_ + h0 + tx * 8;
#pragma unroll
    for (int r = 0; r < 8; r++) {
        float4 v0, v1;
        v0.x = lrelu(acc[r][0]); v0.y = lrelu(acc[r][1]);
        v0.z = lrelu(acc[r][2]); v0.w = lrelu(acc[r][3]);
        v1.x = lrelu(acc[r][4]); v1.y = lrelu(acc[r][5]);
        v1.z = lrelu(acc[r][6]); v1.w = lrelu(acc[r][7]);
        *(float4*)(outp + (size_t)r * H_)     = v0;
        *(float4*)(outp + (size_t)r * H_ + 4) = v1;
    }
}

// ---------------------------------------------------------------------------
// Stage 3: fk = h2 @ W3 + b3, fused with per-tile contraction
//          part[b,tile,o,d] = sum_{i in tile} fk[i,o] * x[i,d]
// Grid: (N/TI, B). Deterministic (no atomics).
// ---------------------------------------------------------------------------
__global__ __launch_bounds__(256)
void k_stage3(const float* __restrict__ x, const float* __restrict__ W3,
              const float* __restrict__ b3) {
    const int i0 = blockIdx.x * TI;
    const int b  = blockIdx.y;

    __shared__ float s_At[TJ][TI + 4];
    __shared__ float s_Wt[TJ][KOUT_];
    __shared__ float s_x[TI][4];
    __shared__ float s_red[8][16][8][3];

    const int t  = threadIdx.x;
    const int tx = t & 15;
    const int ty = t >> 4;

    if (t < TI) {
        const float* xp = x + ((size_t)b * N_ + i0 + t) * 3;
        s_x[t][0] = xp[0]; s_x[t][1] = xp[1]; s_x[t][2] = xp[2];
    }

    float acc[8][8];
#pragma unroll
    for (int r = 0; r < 8; r++)
#pragma unroll
        for (int c = 0; c < 8; c++) acc[r][c] = 0.f;

    const float* A = g_h2 + ((size_t)b * N_ + i0) * H_;

    for (int k0 = 0; k0 < H_; k0 += TJ) {
        __syncthreads();
#pragma unroll
        for (int v = 0; v < 4; v++) {
            int idx = t + v * 256;
            int i   = idx >> 3;
            int c4  = idx & 7;
            float4 w = *(const float4*)&A[(size_t)i * H_ + k0 + c4 * 4];
            s_At[c4 * 4 + 0][i] = w.x;
            s_At[c4 * 4 + 1][i] = w.y;
            s_At[c4 * 4 + 2][i] = w.z;
            s_At[c4 * 4 + 3][i] = w.w;
        }
#pragma unroll
        for (int v = 0; v < 4; v++) {
            int idx = t + v * 256;
            int r   = idx >> 5;
            int c4  = idx & 31;
            *(float4*)&s_Wt[r][c4 * 4] =
                *(const float4*)&W3[(size_t)(k0 + r) * KOUT_ + c4 * 4];
        }
        __syncthreads();
#pragma unroll
        for (int k = 0; k < TJ; k++) {
            float a[8], w[8];
            *(float4*)&a[0] = *(const float4*)&s_At[k][ty * 8];
            *(float4*)&a[4] = *(const float4*)&s_At[k][ty * 8 + 4];
            *(float4*)&w[0] = *(const float4*)&s_Wt[k][tx * 8];
            *(float4*)&w[4] = *(const float4*)&s_Wt[k][tx * 8 + 4];
#pragma unroll
            for (int r = 0; r < 8; r++)
#pragma unroll
                for (int c = 0; c < 8; c++)
                    acc[r][c] = fmaf(a[r], w[c], acc[r][c]);
        }
    }

    // contraction: po[c][d] = sum over this thread's 8 rows of (fk+b3)*x
    float bc[8];
#pragma unroll
    for (int c = 0; c < 8; c++) bc[c] = b3[tx * 8 + c];

    float po[8][3];
#pragma unroll
    for (int c = 0; c < 8; c++) { po[c][0] = 0.f; po[c][1] = 0.f; po[c][2] = 0.f; }
#pragma unroll
    for (int r = 0; r < 8; r++) {
        int il = ty * 8 + r;
        float x0 = s_x[il][0], x1 = s_x[il][1], x2 = s_x[il][2];
#pragma unroll
        for (int c = 0; c < 8; c++) {
            float f = acc[r][c] + bc[c];
            po[c][0] = fmaf(f, x0, po[c][0]);
            po[c][1] = fmaf(f, x1, po[c][1]);
            po[c][2] = fmaf(f, x2, po[c][2]);
        }
    }
    // reduce the two ty values within each warp
#pragma unroll
    for (int c = 0; c < 8; c++)
#pragma unroll
        for (int d = 0; d < 3; d++)
            po[c][d] += __shfl_down_sync(0xffffffffu, po[c][d], 16);

    int lane = t & 31, wp = t >> 5;
    if (lane < 16) {
#pragma unroll
        for (int c = 0; c < 8; c++)
#pragma unroll
            for (int d = 0; d < 3; d++)
                s_red[wp][lane][c][d] = po[c][d];
    }
    __syncthreads();

    if (t < KOUT_) {
        int txo = t >> 3, c = t & 7;
        float s0 = 0.f, s1 = 0.f, s2 = 0.f;
#pragma unroll
        for (int w = 0; w < 8; w++) {
            s0 += s_red[w][txo][c][0];
            s1 += s_red[w][txo][c][1];
            s2 += s_red[w][txo][c][2];
        }
        size_t base = (((size_t)b * NTILES + blockIdx.x) * KOUT_ + t) * 3;
        g_part[base + 0] = s0;
        g_part[base + 1] = s1;
        g_part[base + 2] = s2;
    }
}

// ---------------------------------------------------------------------------
// Stage 4: deterministic reduction over i-tiles, scale by 1/N.
// ---------------------------------------------------------------------------
__global__ void k_reduce(float* __restrict__ out) {
    int t = blockIdx.x * blockDim.x + threadIdx.x;
    if (t >= B_ * KOUT_ * 3) return;
    int b   = t / (KOUT_ * 3);
    int rem = t % (KOUT_ * 3);
    float s = 0.f;
#pragma unroll
    for (int tile = 0; tile < NTILES; tile++)
        s += g_part[((size_t)b * NTILES + tile) * KOUT_ * 3 + rem];
    out[t] = s * (1.0f / N_);
}

// ---------------------------------------------------------------------------
extern "C" void kernel_launch(void* const* d_in, const int* in_sizes, int n_in,
                              void* d_out, int out_size) {
    const float* x     = (const float*)d_in[0];
    const float* u     = (const float*)d_in[1];
    const float* basis = (const float*)d_in[2];
    const float* W1    = (const float*)d_in[3];
    const float* b1    = (const float*)d_in[4];
    const float* W2    = (const float*)d_in[5];
    const float* b2    = (const float*)d_in[6];
    const float* W3    = (const float*)d_in[7];
    const float* b3    = (const float*)d_in[8];
    float* out = (float*)d_out;

    k_stage1<<<dim3(N_ / TI, H_ / TH, B_), 256>>>(x, u, basis, W1, b1);
    k_stage2<<<dim3((B_ * N_) / TI, H_ / TH), 256>>>(W2, b2);
    k_stage3<<<dim3(N_ / TI, B_), 256>>>(x, W3, b3);
    k_reduce<<<(B_ * KOUT_ * 3 + 255) / 256, 256>>>(out);
}

// round 7
// speedup vs baseline: 1.0249x; 1.0249x over previous
#include <cuda_runtime.h>
#include <stdint.h>

// f32x2 packed math is Blackwell-specific; hide the asm from the generic
// compute_103 JIT pass (scalar fallback keeps that pass correct; the exact
// sm_103a cubin is what actually runs).
#if !defined(__CUDA_ARCH__) \
    || defined(__CUDA_ARCH_FEAT_SM103_ALL) \
    || (defined(__CUDA_ARCH_SPECIFIC__) && (__CUDA_ARCH_SPECIFIC__ == 1030)) \
    || (defined(__CUDA_ARCH_FAMILY_SPECIFIC__) && (__CUDA_ARCH_FAMILY_SPECIFIC__ == 1030)) \
    || (defined(__CUDA_ARCH__) && (__CUDA_ARCH__ >= 1000))
#define HAS_F32X2 1
#else
#define HAS_F32X2 0
#endif

// ===========================================================================
// Problem constants
// ===========================================================================
namespace {
constexpr int B_    = 16;
constexpr int N_    = 2048;
constexpr int H_    = 256;
constexpr int KOUT_ = 128;
constexpr int NB_   = 4;
constexpr int NG_   = 2;
constexpr float NEG_ = 0.01f;

constexpr int TI = 128;   // i-tile (rows)
constexpr int TH = 128;   // h-tile (cols)
constexpr int TJ = 32;    // k-tile
constexpr int NTILES = N_ / TI;  // 16
}

// Scratch (allocation-free: device globals)
__device__ float g_h1[(size_t)B_ * N_ * H_];
__device__ float g_h2[(size_t)B_ * N_ * H_];
__device__ float g_part[(size_t)B_ * NTILES * KOUT_ * 3];

// ===========================================================================
// Helpers
// ===========================================================================
__device__ __forceinline__ float fsqrt_fast(float v) {
    float r;
    asm("sqrt.approx.f32 %0, %1;" : "=f"(r) : "f"(v));
    return r;
}
__device__ __forceinline__ float lrelu(float v) { return v > 0.f ? v : NEG_ * v; }

union U64F  { unsigned long long u; float f[2]; };
union F4U2  { float4 f4; unsigned long long u2[2]; };

__device__ __forceinline__ unsigned long long pack2(float lo, float hi) {
    U64F v; v.f[0] = lo; v.f[1] = hi; return v.u;
}
__device__ __forceinline__ unsigned long long pack_dup(float x) {
#if HAS_F32X2
    unsigned long long r;
    asm("mov.b64 %0, {%1, %1};" : "=l"(r) : "r"(__float_as_uint(x)));
    return r;
#else
    return pack2(x, x);
#endif
}
// d = a * b + d, packed 2 x fp32 (FFMA2)
__device__ __forceinline__ void fma2(unsigned long long& d,
                                     unsigned long long a,
                                     unsigned long long b) {
#if HAS_F32X2
    asm("fma.rn.f32x2 %0, %1, %2, %0;" : "+l"(d) : "l"(a), "l"(b));
#else
    U64F dd, aa, bb; dd.u = d; aa.u = a; bb.u = b;
    dd.f[0] = fmaf(aa.f[0], bb.f[0], dd.f[0]);
    dd.f[1] = fmaf(aa.f[1], bb.f[1], dd.f[1]);
    d = dd.u;
#endif
}

// ===========================================================================
// Stage 1: h1[b,i,h] = leaky( base terms + sum_j sqrt(x_i·x_j) · W1d[j,h] )
// Fused: D tile computed on the fly in SMEM. f32x2 packed GEMM core.
// Grid: (N/TI, H/TH, B), 256 threads, 8x8 microtile (as 8x4 f32x2).
// ===========================================================================
__global__ __launch_bounds__(256, 2)
void k_stage1(const float* __restrict__ x, const float* __restrict__ u,
              const float* __restrict__ basis, const float* __restrict__ W1,
              const float* __restrict__ b1) {
    const int i0 = blockIdx.x * TI;
    const int h0 = blockIdx.y * TH;
    const int b  = blockIdx.z;

    __shared__ float s_xi[TI][4];
    __shared__ float s_xj[TJ][4];
    __shared__ float s_Dt[TJ][TI + 4];   // D transposed: [k][i], padded
    __shared__ float s_Wt[TJ][TH];
    __shared__ float s_norm[TI];
    __shared__ float s_proj[TI][NB_];

    const int t  = threadIdx.x;
    const int tx = t & 15;
    const int ty = t >> 4;

    const float* xb = x + (size_t)b * N_ * 3;

    // Per-row scalars (norms, basis projections)
    if (t < TI) {
        float x0 = xb[(i0 + t) * 3 + 0];
        float x1 = xb[(i0 + t) * 3 + 1];
        float x2 = xb[(i0 + t) * 3 + 2];
        s_xi[t][0] = x0; s_xi[t][1] = x1; s_xi[t][2] = x2;
        s_norm[t] = fsqrt_fast(x0 * x0 + x1 * x1 + x2 * x2);
#pragma unroll
        for (int k = 0; k < NB_; k++) {
            const float* bk = basis + ((size_t)b * NB_ + k) * 3;
            s_proj[t][k] = x0 * bk[0] + x1 * bk[1] + x2 * bk[2];
        }
    }
    __syncthreads();

    // Init accumulators with the "small" scalar terms + bias, then pack
    unsigned long long acc2[8][4];
    {
        const float u0 = u[b * NG_ + 0];
        const float u1 = u[b * NG_ + 1];
        float baseh[8], wn[8], wp[NB_][8];
#pragma unroll
        for (int c = 0; c < 8; c++) {
            int h = h0 + tx * 8 + c;
            baseh[c] = b1[h] + u0 * W1[0 * H_ + h] + u1 * W1[1 * H_ + h];
            wn[c] = W1[2 * H_ + h];
#pragma unroll
            for (int k = 0; k < NB_; k++) wp[k][c] = W1[(3 + k) * H_ + h];
        }
#pragma unroll
        for (int r = 0; r < 8; r++) {
            int il = ty * 8 + r;
            float nrm = s_norm[il];
            float p0 = s_proj[il][0], p1 = s_proj[il][1];
            float p2 = s_proj[il][2], p3 = s_proj[il][3];
            float row[8];
#pragma unroll
            for (int c = 0; c < 8; c++) {
                row[c] = baseh[c] + nrm * wn[c]
                       + p0 * wp[0][c] + p1 * wp[1][c]
                       + p2 * wp[2][c] + p3 * wp[3][c];
            }
#pragma unroll
            for (int c2 = 0; c2 < 4; c2++)
                acc2[r][c2] = pack2(row[2 * c2], row[2 * c2 + 1]);
        }
    }

    const float* W1d = W1 + 7 * H_;  // dots block of W1

    for (int j0 = 0; j0 < N_; j0 += TJ) {
        __syncthreads();  // previous GEMM done before overwriting tiles
        if (t < TJ) {
            s_xj[t][0] = xb[(j0 + t) * 3 + 0];
            s_xj[t][1] = xb[(j0 + t) * 3 + 1];
            s_xj[t][2] = xb[(j0 + t) * 3 + 2];
        }
#pragma unroll
        for (int v = 0; v < 4; v++) {
            int idx = t + v * 256;          // float4 id, 0..1023
            int r   = idx >> 5;             // row 0..31
            int c4  = idx & 31;             // col/4
            *(float4*)&s_Wt[r][c4 * 4] =
                *(const float4*)&W1d[(size_t)(j0 + r) * H_ + h0 + c4 * 4];
        }
        __syncthreads();

        // D tile: Dt[k][i] = sqrt(x_{i0+i} . x_{j0+k})
        {
            int k  = t & 31;
            int ib = (t >> 5) * 16;
            float a0 = s_xj[k][0], a1 = s_xj[k][1], a2 = s_xj[k][2];
#pragma unroll
            for (int ii = 0; ii < 16; ii++) {
                int i = ib + ii;
                float d = a0 * s_xi[i][0] + a1 * s_xi[i][1] + a2 * s_xi[i][2];
                s_Dt[k][i] = fsqrt_fast(d);
            }
        }
        __syncthreads();

#pragma unroll
        for (int k = 0; k < TJ; k++) {
            float a[8];
            *(float4*)&a[0] = *(const float4*)&s_Dt[k][ty * 8];
            *(float4*)&a[4] = *(const float4*)&s_Dt[k][ty * 8 + 4];
            F4U2 w01, w23;
            w01.f4 = *(const float4*)&s_Wt[k][tx * 8];
            w23.f4 = *(const float4*)&s_Wt[k][tx * 8 + 4];
            unsigned long long w2[4] = {w01.u2[0], w01.u2[1], w23.u2[0], w23.u2[1]};
            unsigned long long a2[8];
#pragma unroll
            for (int r = 0; r < 8; r++) a2[r] = pack_dup(a[r]);
#pragma unroll
            for (int r = 0; r < 8; r++)
#pragma unroll
                for (int c2 = 0; c2 < 4; c2++)
                    fma2(acc2[r][c2], a2[r], w2[c2]);
        }
    }

    // Epilogue: unpack, LeakyReLU, store h1
    float* outp = g_h1 + ((size_t)b * N_ + i0 + ty * 8) * H_ + h0 + tx * 8;
#pragma unroll
    for (int r = 0; r < 8; r++) {
        U64F e0, e1, e2, e3;
        e0.u = acc2[r][0]; e1.u = acc2[r][1]; e2.u = acc2[r][2]; e3.u = acc2[r][3];
        float4 v0, v1;
        v0.x = lrelu(e0.f[0]); v0.y = lrelu(e0.f[1]);
        v0.z = lrelu(e1.f[0]); v0.w = lrelu(e1.f[1]);
        v1.x = lrelu(e2.f[0]); v1.y = lrelu(e2.f[1]);
        v1.z = lrelu(e3.f[0]); v1.w = lrelu(e3.f[1]);
        *(float4*)(outp + (size_t)r * H_)     = v0;
        *(float4*)(outp + (size_t)r * H_ + 4) = v1;
    }
}

// ===========================================================================
// Stage 2: h2 = leaky(h1 @ W2 + b2).  f32x2 packed GEMM core.
// ===========================================================================
__global__ __launch_bounds__(256, 2)
void k_stage2(const float* __restrict__ W2, const float* __restrict__ b2) {
    const int row0 = blockIdx.x * TI;
    const int h0   = blockIdx.y * TH;

    __shared__ float s_At[TJ][TI + 4];
    __shared__ float s_Wt[TJ][TH];

    const int t  = threadIdx.x;
    const int tx = t & 15;
    const int ty = t >> 4;

    unsigned long long acc2[8][4];
    {
        float bc[8];
#pragma unroll
        for (int c = 0; c < 8; c++) bc[c] = b2[h0 + tx * 8 + c];
        unsigned long long p[4];
#pragma unroll
        for (int c2 = 0; c2 < 4; c2++) p[c2] = pack2(bc[2 * c2], bc[2 * c2 + 1]);
#pragma unroll
        for (int r = 0; r < 8; r++)
#pragma unroll
            for (int c2 = 0; c2 < 4; c2++) acc2[r][c2] = p[c2];
    }

    for (int k0 = 0; k0 < H_; k0 += TJ) {
        __syncthreads();
#pragma unroll
        for (int v = 0; v < 4; v++) {
            int idx = t + v * 256;          // float4 id, 0..1023
            int i   = idx >> 3;             // row 0..127
            int c4  = idx & 7;
            float4 w = *(const float4*)&g_h1[(size_t)(row0 + i) * H_ + k0 + c4 * 4];
            s_At[c4 * 4 + 0][i] = w.x;
            s_At[c4 * 4 + 1][i] = w.y;
            s_At[c4 * 4 + 2][i] = w.z;
            s_At[c4 * 4 + 3][i] = w.w;
        }
#pragma unroll
        for (int v = 0; v < 4; v++) {
            int idx = t + v * 256;
            int r   = idx >> 5;
            int c4  = idx & 31;
            *(float4*)&s_Wt[r][c4 * 4] =
                *(const float4*)&W2[(size_t)(k0 + r) * H_ + h0 + c4 * 4];
        }
        __syncthreads();
#pragma unroll
        for (int k = 0; k < TJ; k++) {
            float a[8];
            *(float4*)&a[0] = *(const float4*)&s_At[k][ty * 8];
            *(float4*)&a[4] = *(const float4*)&s_At[k][ty * 8 + 4];
            F4U2 w01, w23;
            w01.f4 = *(const float4*)&s_Wt[k][tx * 8];
            w23.f4 = *(const float4*)&s_Wt[k][tx * 8 + 4];
            unsigned long long w2[4] = {w01.u2[0], w01.u2[1], w23.u2[0], w23.u2[1]};
            unsigned long long a2[8];
#pragma unroll
            for (int r = 0; r < 8; r++) a2[r] = pack_dup(a[r]);
#pragma unroll
            for (int r = 0; r < 8; r++)
#pragma unroll
                for (int c2 = 0; c2 < 4; c2++)
                    fma2(acc2[r][c2], a2[r], w2[c2]);
        }
    }

    float* outp = g_h2 + ((size_t)row0 + ty * 8) * H_ + h0 + tx * 8;
#pragma unroll
    for (int r = 0; r < 8; r++) {
        U64F e0, e1, e2, e3;
        e0.u = acc2[r][0]; e1.u = acc2[r][1]; e2.u = acc2[r][2]; e3.u = acc2[r][3];
        float4 v0, v1;
        v0.x = lrelu(e0.f[0]); v0.y = lrelu(e0.f[1]);
        v0.z = lrelu(e1.f[0]); v0.w = lrelu(e1.f[1]);
        v1.x = lrelu(e2.f[0]); v1.y = lrelu(e2.f[1]);
        v1.z = lrelu(e3.f[0]); v1.w = lrelu(e3.f[1]);
        *(float4*)(outp + (size_t)r * H_)     = v0;
        *(float4*)(outp + (size_t)r * H_ + 4) = v1;
    }
}

// ===========================================================================
// Stage 3: fk = h2 @ W3 + b3, fused with per-tile contraction
//          part[b,tile,o,d] = sum_{i in tile} fk[i,o] * x[i,d]
// Grid: (N/TI, B). Deterministic (no atomics). f32x2 GEMM core.
// ===========================================================================
__global__ __launch_bounds__(256)
void k_stage3(const float* __restrict__ x, const float* __restrict__ W3,
              const float* __restrict__ b3) {
    const int i0 = blockIdx.x * TI;
    const int b  = blockIdx.y;

    __shared__ float s_At[TJ][TI + 4];
    __shared__ float s_Wt[TJ][KOUT_];
    __shared__ float s_x[TI][4];
    __shared__ float s_red[8][16][8][3];

    const int t  = threadIdx.x;
    const int tx = t & 15;
    const int ty = t >> 4;

    if (t < TI) {
        const float* xp = x + ((size_t)b * N_ + i0 + t) * 3;
        s_x[t][0] = xp[0]; s_x[t][1] = xp[1]; s_x[t][2] = xp[2];
    }

    unsigned long long acc2[8][4];
#pragma unroll
    for (int r = 0; r < 8; r++)
#pragma unroll
        for (int c2 = 0; c2 < 4; c2++) acc2[r][c2] = 0ull;

    const float* A = g_h2 + ((size_t)b * N_ + i0) * H_;

    for (int k0 = 0; k0 < H_; k0 += TJ) {
        __syncthreads();
#pragma unroll
        for (int v = 0; v < 4; v++) {
            int idx = t + v * 256;
            int i   = idx >> 3;
            int c4  = idx & 7;
            float4 w = *(const float4*)&A[(size_t)i * H_ + k0 + c4 * 4];
            s_At[c4 * 4 + 0][i] = w.x;
            s_At[c4 * 4 + 1][i] = w.y;
            s_At[c4 * 4 + 2][i] = w.z;
            s_At[c4 * 4 + 3][i] = w.w;
        }
#pragma unroll
        for (int v = 0; v < 4; v++) {
            int idx = t + v * 256;
            int r   = idx >> 5;
            int c4  = idx & 31;
            *(float4*)&s_Wt[r][c4 * 4] =
                *(const float4*)&W3[(size_t)(k0 + r) * KOUT_ + c4 * 4];
        }
        __syncthreads();
#pragma unroll
        for (int k = 0; k < TJ; k++) {
            float a[8];
            *(float4*)&a[0] = *(const float4*)&s_At[k][ty * 8];
            *(float4*)&a[4] = *(const float4*)&s_At[k][ty * 8 + 4];
            F4U2 w01, w23;
            w01.f4 = *(const float4*)&s_Wt[k][tx * 8];
            w23.f4 = *(const float4*)&s_Wt[k][tx * 8 + 4];
            unsigned long long w2[4] = {w01.u2[0], w01.u2[1], w23.u2[0], w23.u2[1]};
            unsigned long long a2[8];
#pragma unroll
            for (int r = 0; r < 8; r++) a2[r] = pack_dup(a[r]);
#pragma unroll
            for (int r = 0; r < 8; r++)
#pragma unroll
                for (int c2 = 0; c2 < 4; c2++)
                    fma2(acc2[r][c2], a2[r], w2[c2]);
        }
    }

    // unpack accumulators for contraction
    float acc[8][8];
#pragma unroll
    for (int r = 0; r < 8; r++)
#pragma unroll
        for (int c2 = 0; c2 < 4; c2++) {
            U64F e; e.u = acc2[r][c2];
            acc[r][2 * c2]     = e.f[0];
            acc[r][2 * c2 + 1] = e.f[1];
        }

    // contraction: po[c][d] = sum over this thread's 8 rows of (fk+b3)*x
    float bc[8];
#pragma unroll
    for (int c = 0; c < 8; c++) bc[c] = b3[tx * 8 + c];

    float po[8][3];
#pragma unroll
    for (int c = 0; c < 8; c++) { po[c][0] = 0.f; po[c][1] = 0.f; po[c][2] = 0.f; }
#pragma unroll
    for (int r = 0; r < 8; r++) {
        int il = ty * 8 + r;
        float x0 = s_x[il][0], x1 = s_x[il][1], x2 = s_x[il][2];
#pragma unroll
        for (int c = 0; c < 8; c++) {
            float f = acc[r][c] + bc[c];
            po[c][0] = fmaf(f, x0, po[c][0]);
            po[c][1] = fmaf(f, x1, po[c][1]);
            po[c][2] = fmaf(f, x2, po[c][2]);
        }
    }
    // reduce the two ty values within each warp
#pragma unroll
    for (int c = 0; c < 8; c++)
#pragma unroll
        for (int d = 0; d < 3; d++)
            po[c][d] += __shfl_down_sync(0xffffffffu, po[c][d], 16);

    int lane = t & 31, wp = t >> 5;
    if (lane < 16) {
#pragma unroll
        for (int c = 0; c < 8; c++)
#pragma unroll
            for (int d = 0; d < 3; d++)
                s_red[wp][lane][c][d] = po[c][d];
    }
    __syncthreads();

    if (t < KOUT_) {
        int txo = t >> 3, c = t & 7;
        float s0 = 0.f, s1 = 0.f, s2 = 0.f;
#pragma unroll
        for (int w = 0; w < 8; w++) {
            s0 += s_red[w][txo][c][0];
            s1 += s_red[w][txo][c][1];
            s2 += s_red[w][txo][c][2];
        }
        size_t base = (((size_t)b * NTILES + blockIdx.x) * KOUT_ + t) * 3;
        g_part[base + 0] = s0;
        g_part[base + 1] = s1;
        g_part[base + 2] = s2;
    }
}

// ===========================================================================
// Stage 4: deterministic reduction over i-tiles, scale by 1/N.
// ===========================================================================
__global__ void k_reduce(float* __restrict__ out) {
    int t = blockIdx.x * blockDim.x + threadIdx.x;
    if (t >= B_ * KOUT_ * 3) return;
    int b   = t / (KOUT_ * 3);
    int rem = t % (KOUT_ * 3);
    float s = 0.f;
#pragma unroll
    for (int tile = 0; tile < NTILES; tile++)
        s += g_part[((size_t)b * NTILES + tile) * KOUT_ * 3 + rem];
    out[t] = s * (1.0f / N_);
}

// ===========================================================================
extern "C" void kernel_launch(void* const* d_in, const int* in_sizes, int n_in,
                              void* d_out, int out_size) {
    const float* x     = (const float*)d_in[0];
    const float* u     = (const float*)d_in[1];
    const float* basis = (const float*)d_in[2];
    const float* W1    = (const float*)d_in[3];
    const float* b1    = (const float*)d_in[4];
    const float* W2    = (const float*)d_in[5];
    const float* b2    = (const float*)d_in[6];
    const float* W3    = (const float*)d_in[7];
    const float* b3    = (const float*)d_in[8];
    float* out = (float*)d_out;

    k_stage1<<<dim3(N_ / TI, H_ / TH, B_), 256>>>(x, u, basis, W1, b1);
    k_stage2<<<dim3((B_ * N_) / TI, H_ / TH), 256>>>(W2, b2);
    k_stage3<<<dim3(N_ / TI, B_), 256>>>(x, W3, b3);
    k_reduce<<<(B_ * KOUT_ * 3 + 255) / 256, 256>>>(out);
}

// round 9
// speedup vs baseline: 2.0098x; 1.9610x over previous
#include <cuda_runtime.h>
#include <cuda_bf16.h>
#include <stdint.h>

// ===========================================================================
// Problem constants
// ===========================================================================
namespace {
constexpr int B_    = 16;
constexpr int N_    = 2048;
constexpr int H_    = 256;
constexpr int KOUT_ = 128;
constexpr int NB_   = 4;
constexpr int NG_   = 2;
constexpr float NEG_ = 0.01f;

constexpr int TI = 128;            // i-tile rows per CTA
constexpr int NTILES = N_ / TI;    // 16
constexpr int KC = 64;             // j-chunk per mainloop iter
constexpr int NCH = N_ / KC;       // 32

// SMEM row stride for bf16 tiles: 64 data + 8 pad = 72 bf16 = 36 words (144B)
constexpr int SW_BYTES = 144;

// stage-1 dynamic SMEM layout (bytes)
constexpr int OFF_C0   = 0;                    // [256] f32
constexpr int OFF_WN   = 1024;                 // [256] f32
constexpr int OFF_WP   = 2048;                 // [4][256] f32
constexpr int OFF_NORM = 6144;                 // [128] f32
constexpr int OFF_PROJ = 6656;                 // [128][4] f32
constexpr int OFF_XJ   = 8704;                 // [64][3] f32
constexpr int OFF_D    = 9728;                 // Dh: 128 rows * 144B
constexpr int OFF_DL   = OFF_D  + 128 * SW_BYTES;   // 28160
constexpr int OFF_WH   = OFF_DL + 128 * SW_BYTES;   // 46592
constexpr int OFF_WL   = OFF_WH + 256 * SW_BYTES;   // 83456
constexpr int SMEM_SZ1 = OFF_WL + 256 * SW_BYTES;   // 120320

// stage2/3 tiling (fp32 SIMT path)
constexpr int TH = 128;
constexpr int TJ = 32;
}

// Scratch (allocation-free device globals)
__device__ float g_h1[(size_t)B_ * N_ * H_];
__device__ float g_h2[(size_t)B_ * N_ * H_];
__device__ float g_part[(size_t)B_ * NTILES * KOUT_ * 3];
__device__ __nv_bfloat16 g_Wh[(size_t)H_ * N_];   // W1d^T hi: [h][j]
__device__ __nv_bfloat16 g_Wl[(size_t)H_ * N_];   // W1d^T lo

// ===========================================================================
// Helpers
// ===========================================================================
__device__ __forceinline__ float fsqrt_fast(float v) {
    float r;
    asm("sqrt.approx.f32 %0, %1;" : "=f"(r) : "f"(v));
    return r;
}
__device__ __forceinline__ float lrelu(float v) { return v > 0.f ? v : NEG_ * v; }

union Pack8 { __nv_bfloat16 h[8]; uint4 v; };

// Warp-level bf16 tensor-core MMA (sm_80+ portable).
// D(f32) += A(bf16 m16k16 row) * B(bf16 k16n8 col)
__device__ __forceinline__ void mma16816(float* d, const uint32_t* a, const uint32_t* b) {
    asm volatile(
        "mma.sync.aligned.m16n8k16.row.col.f32.bf16.bf16.f32 "
        "{%0,%1,%2,%3}, {%4,%5,%6,%7}, {%8,%9}, {%0,%1,%2,%3};"
        : "+f"(d[0]), "+f"(d[1]), "+f"(d[2]), "+f"(d[3])
        : "r"(a[0]), "r"(a[1]), "r"(a[2]), "r"(a[3]), "r"(b[0]), "r"(b[1]));
}

__device__ __forceinline__ uint32_t lds32(const char* smem, int off) {
    return *(const uint32_t*)(smem + off);
}

// ===========================================================================
// Prep: transpose + split W1 dots block -> g_Wh/g_Wl [h=256][j=2048] bf16
// ===========================================================================
__global__ void k_prep(const float* __restrict__ W1) {
    __shared__ float tile[32][33];
    const int jb = blockIdx.x * 32, hb = blockIdx.y * 32;
    const int tx = threadIdx.x, ty = threadIdx.y;   // 32 x 8
    for (int r = ty; r < 32; r += 8)
        tile[r][tx] = W1[(size_t)(7 + jb + r) * H_ + hb + tx];
    __syncthreads();
    for (int r = ty; r < 32; r += 8) {
        const int h = hb + r, j = jb + tx;
        float v = tile[tx][r];
        __nv_bfloat16 hi = __float2bfloat16_rn(v);
        __nv_bfloat16 lo = __float2bfloat16_rn(v - __bfloat162float(hi));
        g_Wh[(size_t)h * N_ + j] = hi;
        g_Wl[(size_t)h * N_ + j] = lo;
    }
}

// ===========================================================================
// Stage 1 (HMMA mma.sync): h1 = leaky(base + sqrt(x x^T) @ W1d)
// Grid (NTILES, B), 256 threads. Warp tile 64x64, acc in registers (fp32).
// hi/lo bf16 split: Dh*Wh + Dl*Wh + Dh*Wl.
// ===========================================================================
__global__ __launch_bounds__(256, 1)
void k_stage1(const float* __restrict__ x, const float* __restrict__ u,
              const float* __restrict__ basis, const float* __restrict__ W1,
              const float* __restrict__ b1) {
    extern __shared__ char smem[];
    const int t = threadIdx.x, w = t >> 5, lane = t & 31;
    const int i0 = blockIdx.x * TI, b = blockIdx.y;
    const float* xb = x + (size_t)b * N_ * 3;

    float* c0    = (float*)(smem + OFF_C0);
    float* wn    = (float*)(smem + OFF_WN);
    float* wpp   = (float*)(smem + OFF_WP);
    float* snorm = (float*)(smem + OFF_NORM);
    float* sproj = (float*)(smem + OFF_PROJ);
    float* sxj   = (float*)(smem + OFF_XJ);

    // per-(i,h) base terms
    if (t < H_) {
        const float u0 = u[b * NG_ + 0], u1 = u[b * NG_ + 1];
        c0[t] = b1[t] + u0 * W1[t] + u1 * W1[H_ + t];
        wn[t] = W1[2 * H_ + t];
#pragma unroll
        for (int k = 0; k < NB_; k++) wpp[k * H_ + t] = W1[(3 + k) * H_ + t];
    }

    // per-row x_i for D production: thread t owns row t>>1, j-half t&1
    const int drow = t >> 1;
    const int jh   = t & 1;
    const float xi0 = xb[(i0 + drow) * 3 + 0];
    const float xi1 = xb[(i0 + drow) * 3 + 1];
    const float xi2 = xb[(i0 + drow) * 3 + 2];

    // scalar base terms for row t (FIX: load row t's own x, NOT the D-production
    // registers which hold row t>>1 — that was R8's 8.7e-3 bug)
    if (t < TI) {
        const float y0 = xb[(i0 + t) * 3 + 0];
        const float y1 = xb[(i0 + t) * 3 + 1];
        const float y2 = xb[(i0 + t) * 3 + 2];
        snorm[t] = fsqrt_fast(y0 * y0 + y1 * y1 + y2 * y2);
#pragma unroll
        for (int k = 0; k < NB_; k++) {
            const float* bk = basis + ((size_t)b * NB_ + k) * 3;
            sproj[t * NB_ + k] = y0 * bk[0] + y1 * bk[1] + y2 * bk[2];
        }
    }

    // warp output tile: rows (w&1)*64, cols (w>>1)*64
    const int wrow = (w & 1) * 64;
    const int wcol = (w >> 1) * 64;
    const int g = lane >> 2;     // 0..7
    const int c = lane & 3;      // 0..3

    float acc[4][8][4];          // [mi][ni][reg], 128 fp32
#pragma unroll
    for (int mi = 0; mi < 4; mi++)
#pragma unroll
        for (int ni = 0; ni < 8; ni++)
#pragma unroll
            for (int e = 0; e < 4; e++) acc[mi][ni][e] = 0.f;

    for (int ch = 0; ch < NCH; ch++) {
        const int j0 = ch * KC;
        __syncthreads();   // previous chunk's mma done before overwriting tiles

        // x_j chunk to smem
        if (t < 192) sxj[t] = xb[j0 * 3 + t];

        // W chunk (hi & lo): 256 rows x 64 bf16, 16B segments
#pragma unroll
        for (int m = 0; m < 8; m++) {
            const int q   = t + m * 256;      // 0..2047
            const int row = q >> 3, seg = q & 7;
            const int dst = row * SW_BYTES + seg * 16;
            *(uint4*)(smem + OFF_WH + dst) =
                *(const uint4*)(g_Wh + (size_t)row * N_ + j0 + seg * 8);
            *(uint4*)(smem + OFF_WL + dst) =
                *(const uint4*)(g_Wl + (size_t)row * N_ + j0 + seg * 8);
        }
        __syncthreads();   // sxj visible

        // produce D tile rows: sqrt(x_i . x_j), bf16 hi/lo split
#pragma unroll
        for (int g4 = 0; g4 < 4; g4++) {
            Pack8 hi, lo;
#pragma unroll
            for (int e = 0; e < 8; e++) {
                const int jl = jh * 32 + g4 * 8 + e;
                const float d = sxj[jl * 3 + 0] * xi0 + sxj[jl * 3 + 1] * xi1
                              + sxj[jl * 3 + 2] * xi2;
                const float s = fsqrt_fast(d);
                __nv_bfloat16 h16 = __float2bfloat16_rn(s);
                hi.h[e] = h16;
                lo.h[e] = __float2bfloat16_rn(s - __bfloat162float(h16));
            }
            const int dst = drow * SW_BYTES + (jh * 32 + g4 * 8) * 2;
            *(uint4*)(smem + OFF_D  + dst) = hi.v;
            *(uint4*)(smem + OFF_DL + dst) = lo.v;
        }
        __syncthreads();

        // MMA phase: 4 k16 steps
#pragma unroll
        for (int k16 = 0; k16 < 4; k16++) {
            const int wb = (k16 * 8 + c) * 4;      // byte offset of word c
            // B fragments resident (8 n-tiles, hi+lo)
            uint32_t bh[8][2], bl[8][2];
#pragma unroll
            for (int ni = 0; ni < 8; ni++) {
                const int rb = (wcol + ni * 8 + g) * SW_BYTES;
                bh[ni][0] = lds32(smem, OFF_WH + rb + wb);
                bh[ni][1] = lds32(smem, OFF_WH + rb + wb + 16);
                bl[ni][0] = lds32(smem, OFF_WL + rb + wb);
                bl[ni][1] = lds32(smem, OFF_WL + rb + wb + 16);
            }
#pragma unroll
            for (int mi = 0; mi < 4; mi++) {
                const int r0 = (wrow + mi * 16 + g) * SW_BYTES;
                const int r8 = r0 + 8 * SW_BYTES;
                uint32_t ah[4], al[4];
                ah[0] = lds32(smem, OFF_D  + r0 + wb);
                ah[1] = lds32(smem, OFF_D  + r8 + wb);
                ah[2] = lds32(smem, OFF_D  + r0 + wb + 16);
                ah[3] = lds32(smem, OFF_D  + r8 + wb + 16);
                al[0] = lds32(smem, OFF_DL + r0 + wb);
                al[1] = lds32(smem, OFF_DL + r8 + wb);
                al[2] = lds32(smem, OFF_DL + r0 + wb + 16);
                al[3] = lds32(smem, OFF_DL + r8 + wb + 16);
#pragma unroll
                for (int ni = 0; ni < 8; ni++) {
                    mma16816(acc[mi][ni], ah, bh[ni]);
                    mma16816(acc[mi][ni], al, bh[ni]);
                    mma16816(acc[mi][ni], ah, bl[ni]);
                }
            }
        }
    }

    // Epilogue: add exact fp32 base terms, LeakyReLU, store
#pragma unroll
    for (int mi = 0; mi < 4; mi++) {
#pragma unroll
        for (int rr = 0; rr < 2; rr++) {
            const int row = wrow + mi * 16 + g + rr * 8;
            const float nrm = snorm[row];
            const float p0 = sproj[row * NB_ + 0], p1 = sproj[row * NB_ + 1];
            const float p2 = sproj[row * NB_ + 2], p3 = sproj[row * NB_ + 3];
            float* outp = g_h1 + ((size_t)b * N_ + i0 + row) * H_;
#pragma unroll
            for (int ni = 0; ni < 8; ni++) {
                const int col = wcol + ni * 8 + c * 2;
                float2 v;
                {
                    const int h = col;
                    float z = acc[mi][ni][rr * 2 + 0] + c0[h] + nrm * wn[h]
                            + p0 * wpp[h] + p1 * wpp[H_ + h]
                            + p2 * wpp[2 * H_ + h] + p3 * wpp[3 * H_ + h];
                    v.x = lrelu(z);
                }
                {
                    const int h = col + 1;
                    float z = acc[mi][ni][rr * 2 + 1] + c0[h] + nrm * wn[h]
                            + p0 * wpp[h] + p1 * wpp[H_ + h]
                            + p2 * wpp[2 * H_ + h] + p3 * wpp[3 * H_ + h];
                    v.y = lrelu(z);
                }
                *(float2*)(outp + col) = v;
            }
        }
    }
}

// ===========================================================================
// Stage 2: h2 = leaky(h1 @ W2 + b2)   (fp32 SIMT, passing version)
// ===========================================================================
__global__ __launch_bounds__(256, 2)
void k_stage2(const float* __restrict__ W2, const float* __restrict__ b2) {
    const int row0 = blockIdx.x * TI;
    const int h0   = blockIdx.y * TH;
    __shared__ float s_At[TJ][TI + 4];
    __shared__ float s_Wt[TJ][TH];
    const int t = threadIdx.x, tx = t & 15, ty = t >> 4;

    float acc[8][8];
    {
        float bc[8];
#pragma unroll
        for (int c = 0; c < 8; c++) bc[c] = b2[h0 + tx * 8 + c];
#pragma unroll
        for (int r = 0; r < 8; r++)
#pragma unroll
            for (int c = 0; c < 8; c++) acc[r][c] = bc[c];
    }
    for (int k0 = 0; k0 < H_; k0 += TJ) {
        __syncthreads();
#pragma unroll
        for (int v = 0; v < 4; v++) {
            int idx = t + v * 256, i = idx >> 3, c4 = idx & 7;
            float4 wv = *(const float4*)&g_h1[(size_t)(row0 + i) * H_ + k0 + c4 * 4];
            s_At[c4 * 4 + 0][i] = wv.x; s_At[c4 * 4 + 1][i] = wv.y;
            s_At[c4 * 4 + 2][i] = wv.z; s_At[c4 * 4 + 3][i] = wv.w;
        }
#pragma unroll
        for (int v = 0; v < 4; v++) {
            int idx = t + v * 256, r = idx >> 5, c4 = idx & 31;
            *(float4*)&s_Wt[r][c4 * 4] = *(const float4*)&W2[(size_t)(k0 + r) * H_ + h0 + c4 * 4];
        }
        __syncthreads();
#pragma unroll
        for (int k = 0; k < TJ; k++) {
            float a[8], wv[8];
            *(float4*)&a[0] = *(const float4*)&s_At[k][ty * 8];
            *(float4*)&a[4] = *(const float4*)&s_At[k][ty * 8 + 4];
            *(float4*)&wv[0] = *(const float4*)&s_Wt[k][tx * 8];
            *(float4*)&wv[4] = *(const float4*)&s_Wt[k][tx * 8 + 4];
#pragma unroll
            for (int r = 0; r < 8; r++)
#pragma unroll
                for (int c = 0; c < 8; c++) acc[r][c] = fmaf(a[r], wv[c], acc[r][c]);
        }
    }
    float* outp = g_h2 + ((size_t)row0 + ty * 8) * H_ + h0 + tx * 8;
#pragma unroll
    for (int r = 0; r < 8; r++) {
        float4 v0, v1;
        v0.x = lrelu(acc[r][0]); v0.y = lrelu(acc[r][1]); v0.z = lrelu(acc[r][2]); v0.w = lrelu(acc[r][3]);
        v1.x = lrelu(acc[r][4]); v1.y = lrelu(acc[r][5]); v1.z = lrelu(acc[r][6]); v1.w = lrelu(acc[r][7]);
        *(float4*)(outp + (size_t)r * H_)     = v0;
        *(float4*)(outp + (size_t)r * H_ + 4) = v1;
    }
}

// ===========================================================================
// Stage 3: fk = h2 @ W3 + b3 fused with per-tile contraction (passing version)
// ===========================================================================
__global__ __launch_bounds__(256)
void k_stage3(const float* __restrict__ x, const float* __restrict__ W3,
              const float* __restrict__ b3) {
    const int i0 = blockIdx.x * TI;
    const int b  = blockIdx.y;
    __shared__ float s_At[TJ][TI + 4];
    __shared__ float s_Wt[TJ][KOUT_];
    __shared__ float s_x[TI][4];
    __shared__ float s_red[8][16][8][3];
    const int t = threadIdx.x, tx = t & 15, ty = t >> 4;

    if (t < TI) {
        const float* xp = x + ((size_t)b * N_ + i0 + t) * 3;
        s_x[t][0] = xp[0]; s_x[t][1] = xp[1]; s_x[t][2] = xp[2];
    }
    float acc[8][8];
#pragma unroll
    for (int r = 0; r < 8; r++)
#pragma unroll
        for (int c = 0; c < 8; c++) acc[r][c] = 0.f;

    const float* A = g_h2 + ((size_t)b * N_ + i0) * H_;
    for (int k0 = 0; k0 < H_; k0 += TJ) {
        __syncthreads();
#pragma unroll
        for (int v = 0; v < 4; v++) {
            int idx = t + v * 256, i = idx >> 3, c4 = idx & 7;
            float4 wv = *(const float4*)&A[(size_t)i * H_ + k0 + c4 * 4];
            s_At[c4 * 4 + 0][i] = wv.x; s_At[c4 * 4 + 1][i] = wv.y;
            s_At[c4 * 4 + 2][i] = wv.z; s_At[c4 * 4 + 3][i] = wv.w;
        }
#pragma unroll
        for (int v = 0; v < 4; v++) {
            int idx = t + v * 256, r = idx >> 5, c4 = idx & 31;
            *(float4*)&s_Wt[r][c4 * 4] = *(const float4*)&W3[(size_t)(k0 + r) * KOUT_ + c4 * 4];
        }
        __syncthreads();
#pragma unroll
        for (int k = 0; k < TJ; k++) {
            float a[8], wv[8];
            *(float4*)&a[0] = *(const float4*)&s_At[k][ty * 8];
            *(float4*)&a[4] = *(const float4*)&s_At[k][ty * 8 + 4];
            *(float4*)&wv[0] = *(const float4*)&s_Wt[k][tx * 8];
            *(float4*)&wv[4] = *(const float4*)&s_Wt[k][tx * 8 + 4];
#pragma unroll
            for (int r = 0; r < 8; r++)
#pragma unroll
                for (int c = 0; c < 8; c++) acc[r][c] = fmaf(a[r], wv[c], acc[r][c]);
        }
    }
    float bc[8];
#pragma unroll
    for (int c = 0; c < 8; c++) bc[c] = b3[tx * 8 + c];
    float po[8][3];
#pragma unroll
    for (int c = 0; c < 8; c++) { po[c][0] = 0.f; po[c][1] = 0.f; po[c][2] = 0.f; }
#pragma unroll
    for (int r = 0; r < 8; r++) {
        int ilr = ty * 8 + r;
        float x0 = s_x[ilr][0], x1 = s_x[ilr][1], x2 = s_x[ilr][2];
#pragma unroll
        for (int c = 0; c < 8; c++) {
            float f = acc[r][c] + bc[c];
            po[c][0] = fmaf(f, x0, po[c][0]);
            po[c][1] = fmaf(f, x1, po[c][1]);
            po[c][2] = fmaf(f, x2, po[c][2]);
        }
    }
#pragma unroll
    for (int c = 0; c < 8; c++)
#pragma unroll
        for (int d = 0; d < 3; d++)
            po[c][d] += __shfl_down_sync(0xffffffffu, po[c][d], 16);
    int lane = t & 31, wp = t >> 5;
    if (lane < 16) {
#pragma unroll
        for (int c = 0; c < 8; c++)
#pragma unroll
            for (int d = 0; d < 3; d++) s_red[wp][lane][c][d] = po[c][d];
    }
    __syncthreads();
    if (t < KOUT_) {
        int txo = t >> 3, c = t & 7;
        float s0 = 0.f, s1 = 0.f, s2 = 0.f;
#pragma unroll
        for (int ww = 0; ww < 8; ww++) {
            s0 += s_red[ww][txo][c][0];
            s1 += s_red[ww][txo][c][1];
            s2 += s_red[ww][txo][c][2];
        }
        size_t base = (((size_t)b * NTILES + blockIdx.x) * KOUT_ + t) * 3;
        g_part[base + 0] = s0; g_part[base + 1] = s1; g_part[base + 2] = s2;
    }
}

// ===========================================================================
// Stage 4: reduce tiles
// ===========================================================================
__global__ void k_reduce(float* __restrict__ out) {
    int t = blockIdx.x * blockDim.x + threadIdx.x;
    if (t >= B_ * KOUT_ * 3) return;
    int b = t / (KOUT_ * 3), rem = t % (KOUT_ * 3);
    float s = 0.f;
#pragma unroll
    for (int tile = 0; tile < NTILES; tile++)
        s += g_part[((size_t)b * NTILES + tile) * KOUT_ * 3 + rem];
    out[t] = s * (1.0f / N_);
}

// ===========================================================================
extern "C" void kernel_launch(void* const* d_in, const int* in_sizes, int n_in,
                              void* d_out, int out_size) {
    const float* x     = (const float*)d_in[0];
    const float* u     = (const float*)d_in[1];
    const float* basis = (const float*)d_in[2];
    const float* W1    = (const float*)d_in[3];
    const float* b1    = (const float*)d_in[4];
    const float* W2    = (const float*)d_in[5];
    const float* b2    = (const float*)d_in[6];
    const float* W3    = (const float*)d_in[7];
    const float* b3    = (const float*)d_in[8];
    float* out = (float*)d_out;

    cudaFuncSetAttribute(k_stage1, cudaFuncAttributeMaxDynamicSharedMemorySize, SMEM_SZ1);

    k_prep<<<dim3(N_ / 32, H_ / 32), dim3(32, 8)>>>(W1);
    k_stage1<<<dim3(NTILES, B_), 256, SMEM_SZ1>>>(x, u, basis, W1, b1);
    k_stage2<<<dim3((B_ * N_) / TI, H_ / TH), 256>>>(W2, b2);
    k_stage3<<<dim3(N_ / TI, B_), 256>>>(x, W3, b3);
    k_reduce<<<(B_ * KOUT_ * 3 + 255) / 256, 256>>>(out);
}

// round 10
// speedup vs baseline: 2.3518x; 1.1702x over previous
#include <cuda_runtime.h>
#include <cuda_bf16.h>
#include <stdint.h>

// ===========================================================================
// Problem constants
// ===========================================================================
namespace {
constexpr int B_    = 16;
constexpr int N_    = 2048;
constexpr int H_    = 256;
constexpr int KOUT_ = 128;
constexpr int NB_   = 4;
constexpr int NG_   = 2;
constexpr float NEG_ = 0.01f;

constexpr int TI = 128;            // i-tile rows per CTA
constexpr int NTILES = N_ / TI;    // 16
constexpr int KC = 64;             // k-chunk
constexpr int NCH = N_ / KC;       // 32 (stage1)

constexpr int SW_BYTES = 144;      // 64 bf16 + 8 pad -> conflict-free frags

// stage-1 smem layout (bytes)
constexpr int OFF_C0   = 0;
constexpr int OFF_WN   = 1024;
constexpr int OFF_WP   = 2048;
constexpr int OFF_NORM = 6144;
constexpr int OFF_PROJ = 6656;
constexpr int OFF_XJ   = 8704;
constexpr int OFF_D    = 9728;
constexpr int OFF_DL   = OFF_D  + 128 * SW_BYTES;
constexpr int OFF_WH   = OFF_DL + 128 * SW_BYTES;
constexpr int OFF_WL   = OFF_WH + 256 * SW_BYTES;
constexpr int SMEM_SZ1 = OFF_WL + 256 * SW_BYTES;   // 120320

// stage-2 smem layout
constexpr int OFF2_C0 = 0;                          // [256] f32 bias
constexpr int OFF2_A  = 1024;
constexpr int OFF2_AL = OFF2_A  + 128 * SW_BYTES;
constexpr int OFF2_WH = OFF2_AL + 128 * SW_BYTES;
constexpr int OFF2_WL = OFF2_WH + 256 * SW_BYTES;
constexpr int SMEM_SZ2 = OFF2_WL + 256 * SW_BYTES;  // 111616

// stage-3 smem layout
constexpr int OFF3_X   = 0;                          // [128][4] f32
constexpr int OFF3_RED = 2048;                       // [8][4][8][3] f32
constexpr int OFF3_A   = 5120;
constexpr int OFF3_AL  = OFF3_A  + 128 * SW_BYTES;
constexpr int OFF3_WH  = OFF3_AL + 128 * SW_BYTES;
constexpr int OFF3_WL  = OFF3_WH + 128 * SW_BYTES;
constexpr int SMEM_SZ3 = OFF3_WL + 128 * SW_BYTES;   // 78848
}

// Scratch (allocation-free device globals)
__device__ __nv_bfloat16 g_h1h[(size_t)B_ * N_ * H_];
__device__ __nv_bfloat16 g_h1l[(size_t)B_ * N_ * H_];
__device__ __nv_bfloat16 g_h2h[(size_t)B_ * N_ * H_];
__device__ __nv_bfloat16 g_h2l[(size_t)B_ * N_ * H_];
__device__ float g_part[(size_t)B_ * NTILES * KOUT_ * 3];
__device__ __nv_bfloat16 g_Wh [(size_t)H_ * N_];       // W1d^T hi [h][j]
__device__ __nv_bfloat16 g_Wl [(size_t)H_ * N_];
__device__ __nv_bfloat16 g_W2h[(size_t)H_ * H_];       // W2^T hi [hout][hin]
__device__ __nv_bfloat16 g_W2l[(size_t)H_ * H_];
__device__ __nv_bfloat16 g_W3h[(size_t)KOUT_ * H_];    // W3^T hi [o][h]
__device__ __nv_bfloat16 g_W3l[(size_t)KOUT_ * H_];

// ===========================================================================
// Helpers
// ===========================================================================
__device__ __forceinline__ float fsqrt_fast(float v) {
    float r;
    asm("sqrt.approx.f32 %0, %1;" : "=f"(r) : "f"(v));
    return r;
}
__device__ __forceinline__ float lrelu(float v) { return v > 0.f ? v : NEG_ * v; }

union Pack8 { __nv_bfloat16 h[8]; uint4 v; };

__device__ __forceinline__ void mma16816(float* d, const uint32_t* a, const uint32_t* b) {
    asm volatile(
        "mma.sync.aligned.m16n8k16.row.col.f32.bf16.bf16.f32 "
        "{%0,%1,%2,%3}, {%4,%5,%6,%7}, {%8,%9}, {%0,%1,%2,%3};"
        : "+f"(d[0]), "+f"(d[1]), "+f"(d[2]), "+f"(d[3])
        : "r"(a[0]), "r"(a[1]), "r"(a[2]), "r"(a[3]), "r"(b[0]), "r"(b[1]));
}
__device__ __forceinline__ uint32_t lds32(const char* smem, int off) {
    return *(const uint32_t*)(smem + off);
}
// split z -> hi/lo bf16 pair packed per 2 cols
__device__ __forceinline__ void split_store2(__nv_bfloat16* ph, __nv_bfloat16* pl,
                                             size_t idx, float z0, float z1) {
    __nv_bfloat16 h0 = __float2bfloat16_rn(z0);
    __nv_bfloat16 h1 = __float2bfloat16_rn(z1);
    __nv_bfloat162 vh; vh.x = h0; vh.y = h1;
    __nv_bfloat162 vl;
    vl.x = __float2bfloat16_rn(z0 - __bfloat162float(h0));
    vl.y = __float2bfloat16_rn(z1 - __bfloat162float(h1));
    *reinterpret_cast<__nv_bfloat162*>(ph + idx) = vh;
    *reinterpret_cast<__nv_bfloat162*>(pl + idx) = vl;
}

// ===========================================================================
// Prep: transpose + hi/lo split:  dst[c][r] = split(src[r][c]),  src [R][C]
// grid (R/32, C/32), block (32, 8)
// ===========================================================================
__global__ void k_prep_t(const float* __restrict__ src, __nv_bfloat16* dh,
                         __nv_bfloat16* dl, int R, int C) {
    __shared__ float tile[32][33];
    const int rb = blockIdx.x * 32, cb = blockIdx.y * 32;
    const int tx = threadIdx.x, ty = threadIdx.y;
    for (int r = ty; r < 32; r += 8)
        tile[r][tx] = src[(size_t)(rb + r) * C + cb + tx];
    __syncthreads();
    for (int r = ty; r < 32; r += 8) {
        const int cc = cb + r, rr = rb + tx;
        float v = tile[tx][r];
        __nv_bfloat16 hi = __float2bfloat16_rn(v);
        dh[(size_t)cc * R + rr] = hi;
        dl[(size_t)cc * R + rr] = __float2bfloat16_rn(v - __bfloat162float(hi));
    }
}

// ===========================================================================
// Stage 1 (HMMA): h1 = leaky(base + sqrt(x x^T) @ W1d) -> bf16 hi/lo
// Grid (NTILES, B), 256 threads.  (frozen from R9 except epilogue stores)
// ===========================================================================
__global__ __launch_bounds__(256, 1)
void k_stage1(const float* __restrict__ x, const float* __restrict__ u,
              const float* __restrict__ basis, const float* __restrict__ W1,
              const float* __restrict__ b1) {
    extern __shared__ char smem[];
    const int t = threadIdx.x, w = t >> 5, lane = t & 31;
    const int i0 = blockIdx.x * TI, b = blockIdx.y;
    const float* xb = x + (size_t)b * N_ * 3;

    float* c0    = (float*)(smem + OFF_C0);
    float* wn    = (float*)(smem + OFF_WN);
    float* wpp   = (float*)(smem + OFF_WP);
    float* snorm = (float*)(smem + OFF_NORM);
    float* sproj = (float*)(smem + OFF_PROJ);
    float* sxj   = (float*)(smem + OFF_XJ);

    if (t < H_) {
        const float u0 = u[b * NG_ + 0], u1 = u[b * NG_ + 1];
        c0[t] = b1[t] + u0 * W1[t] + u1 * W1[H_ + t];
        wn[t] = W1[2 * H_ + t];
#pragma unroll
        for (int k = 0; k < NB_; k++) wpp[k * H_ + t] = W1[(3 + k) * H_ + t];
    }

    const int drow = t >> 1;
    const int jh   = t & 1;
    const float xi0 = xb[(i0 + drow) * 3 + 0];
    const float xi1 = xb[(i0 + drow) * 3 + 1];
    const float xi2 = xb[(i0 + drow) * 3 + 2];

    if (t < TI) {
        const float y0 = xb[(i0 + t) * 3 + 0];
        const float y1 = xb[(i0 + t) * 3 + 1];
        const float y2 = xb[(i0 + t) * 3 + 2];
        snorm[t] = fsqrt_fast(y0 * y0 + y1 * y1 + y2 * y2);
#pragma unroll
        for (int k = 0; k < NB_; k++) {
            const float* bk = basis + ((size_t)b * NB_ + k) * 3;
            sproj[t * NB_ + k] = y0 * bk[0] + y1 * bk[1] + y2 * bk[2];
        }
    }

    const int wrow = (w & 1) * 64;
    const int wcol = (w >> 1) * 64;
    const int g = lane >> 2;
    const int c = lane & 3;

    float acc[4][8][4];
#pragma unroll
    for (int mi = 0; mi < 4; mi++)
#pragma unroll
        for (int ni = 0; ni < 8; ni++)
#pragma unroll
            for (int e = 0; e < 4; e++) acc[mi][ni][e] = 0.f;

    for (int ch = 0; ch < NCH; ch++) {
        const int j0 = ch * KC;
        __syncthreads();

        if (t < 192) sxj[t] = xb[j0 * 3 + t];

#pragma unroll
        for (int m = 0; m < 8; m++) {
            const int q   = t + m * 256;
            const int row = q >> 3, seg = q & 7;
            const int dst = row * SW_BYTES + seg * 16;
            *(uint4*)(smem + OFF_WH + dst) =
                *(const uint4*)(g_Wh + (size_t)row * N_ + j0 + seg * 8);
            *(uint4*)(smem + OFF_WL + dst) =
                *(const uint4*)(g_Wl + (size_t)row * N_ + j0 + seg * 8);
        }
        __syncthreads();

#pragma unroll
        for (int g4 = 0; g4 < 4; g4++) {
            Pack8 hi, lo;
#pragma unroll
            for (int e = 0; e < 8; e++) {
                const int jl = jh * 32 + g4 * 8 + e;
                const float d = sxj[jl * 3 + 0] * xi0 + sxj[jl * 3 + 1] * xi1
                              + sxj[jl * 3 + 2] * xi2;
                const float s = fsqrt_fast(d);
                __nv_bfloat16 h16 = __float2bfloat16_rn(s);
                hi.h[e] = h16;
                lo.h[e] = __float2bfloat16_rn(s - __bfloat162float(h16));
            }
            const int dst = drow * SW_BYTES + (jh * 32 + g4 * 8) * 2;
            *(uint4*)(smem + OFF_D  + dst) = hi.v;
            *(uint4*)(smem + OFF_DL + dst) = lo.v;
        }
        __syncthreads();

#pragma unroll
        for (int k16 = 0; k16 < 4; k16++) {
            const int wb = (k16 * 8 + c) * 4;
            uint32_t bh[8][2], bl[8][2];
#pragma unroll
            for (int ni = 0; ni < 8; ni++) {
                const int rb = (wcol + ni * 8 + g) * SW_BYTES;
                bh[ni][0] = lds32(smem, OFF_WH + rb + wb);
                bh[ni][1] = lds32(smem, OFF_WH + rb + wb + 16);
                bl[ni][0] = lds32(smem, OFF_WL + rb + wb);
                bl[ni][1] = lds32(smem, OFF_WL + rb + wb + 16);
            }
#pragma unroll
            for (int mi = 0; mi < 4; mi++) {
                const int r0 = (wrow + mi * 16 + g) * SW_BYTES;
                const int r8 = r0 + 8 * SW_BYTES;
                uint32_t ah[4], al[4];
                ah[0] = lds32(smem, OFF_D  + r0 + wb);
                ah[1] = lds32(smem, OFF_D  + r8 + wb);
                ah[2] = lds32(smem, OFF_D  + r0 + wb + 16);
                ah[3] = lds32(smem, OFF_D  + r8 + wb + 16);
                al[0] = lds32(smem, OFF_DL + r0 + wb);
                al[1] = lds32(smem, OFF_DL + r8 + wb);
                al[2] = lds32(smem, OFF_DL + r0 + wb + 16);
                al[3] = lds32(smem, OFF_DL + r8 + wb + 16);
#pragma unroll
                for (int ni = 0; ni < 8; ni++) {
                    mma16816(acc[mi][ni], ah, bh[ni]);
                    mma16816(acc[mi][ni], al, bh[ni]);
                    mma16816(acc[mi][ni], ah, bl[ni]);
                }
            }
        }
    }

    // Epilogue: exact fp32 base terms, LeakyReLU, store bf16 hi/lo
#pragma unroll
    for (int mi = 0; mi < 4; mi++) {
#pragma unroll
        for (int rr = 0; rr < 2; rr++) {
            const int row = wrow + mi * 16 + g + rr * 8;
            const float nrm = snorm[row];
            const float p0 = sproj[row * NB_ + 0], p1 = sproj[row * NB_ + 1];
            const float p2 = sproj[row * NB_ + 2], p3 = sproj[row * NB_ + 3];
            const size_t rbase = ((size_t)b * N_ + i0 + row) * H_;
#pragma unroll
            for (int ni = 0; ni < 8; ni++) {
                const int col = wcol + ni * 8 + c * 2;
                float z[2];
#pragma unroll
                for (int e = 0; e < 2; e++) {
                    const int h = col + e;
                    float zz = acc[mi][ni][rr * 2 + e] + c0[h] + nrm * wn[h]
                             + p0 * wpp[h] + p1 * wpp[H_ + h]
                             + p2 * wpp[2 * H_ + h] + p3 * wpp[3 * H_ + h];
                    z[e] = lrelu(zz);
                }
                split_store2(g_h1h, g_h1l, rbase + col, z[0], z[1]);
            }
        }
    }
}

// ===========================================================================
// Stage 2 (HMMA): h2 = leaky(h1 @ W2 + b2) -> bf16 hi/lo
// Grid (B*N/TI), 256 threads. K = 256 (4 chunks).
// ===========================================================================
__global__ __launch_bounds__(256, 1)
void k_stage2(const float* __restrict__ b2) {
    extern __shared__ char smem[];
    const int t = threadIdx.x, w = t >> 5, lane = t & 31;
    const size_t row0 = (size_t)blockIdx.x * TI;

    float* c0 = (float*)(smem + OFF2_C0);
    if (t < H_) c0[t] = b2[t];

    const int wrow = (w & 1) * 64;
    const int wcol = (w >> 1) * 64;
    const int g = lane >> 2;
    const int c = lane & 3;

    float acc[4][8][4];
#pragma unroll
    for (int mi = 0; mi < 4; mi++)
#pragma unroll
        for (int ni = 0; ni < 8; ni++)
#pragma unroll
            for (int e = 0; e < 4; e++) acc[mi][ni][e] = 0.f;

    for (int ch = 0; ch < 4; ch++) {
        const int k0 = ch * KC;
        __syncthreads();

        // A chunk (h1 hi/lo): 128 rows x 64
#pragma unroll
        for (int m = 0; m < 4; m++) {
            const int q = t + m * 256;
            const int row = q >> 3, seg = q & 7;
            const int dst = row * SW_BYTES + seg * 16;
            const size_t src = (row0 + row) * H_ + k0 + seg * 8;
            *(uint4*)(smem + OFF2_A  + dst) = *(const uint4*)(g_h1h + src);
            *(uint4*)(smem + OFF2_AL + dst) = *(const uint4*)(g_h1l + src);
        }
        // W2 chunk: 256 rows x 64
#pragma unroll
        for (int m = 0; m < 8; m++) {
            const int q = t + m * 256;
            const int row = q >> 3, seg = q & 7;
            const int dst = row * SW_BYTES + seg * 16;
            const size_t src = (size_t)row * H_ + k0 + seg * 8;
            *(uint4*)(smem + OFF2_WH + dst) = *(const uint4*)(g_W2h + src);
            *(uint4*)(smem + OFF2_WL + dst) = *(const uint4*)(g_W2l + src);
        }
        __syncthreads();

#pragma unroll
        for (int k16 = 0; k16 < 4; k16++) {
            const int wb = (k16 * 8 + c) * 4;
            uint32_t bh[8][2], bl[8][2];
#pragma unroll
            for (int ni = 0; ni < 8; ni++) {
                const int rb = (wcol + ni * 8 + g) * SW_BYTES;
                bh[ni][0] = lds32(smem, OFF2_WH + rb + wb);
                bh[ni][1] = lds32(smem, OFF2_WH + rb + wb + 16);
                bl[ni][0] = lds32(smem, OFF2_WL + rb + wb);
                bl[ni][1] = lds32(smem, OFF2_WL + rb + wb + 16);
            }
#pragma unroll
            for (int mi = 0; mi < 4; mi++) {
                const int r0 = (wrow + mi * 16 + g) * SW_BYTES;
                const int r8 = r0 + 8 * SW_BYTES;
                uint32_t ah[4], al[4];
                ah[0] = lds32(smem, OFF2_A  + r0 + wb);
                ah[1] = lds32(smem, OFF2_A  + r8 + wb);
                ah[2] = lds32(smem, OFF2_A  + r0 + wb + 16);
                ah[3] = lds32(smem, OFF2_A  + r8 + wb + 16);
                al[0] = lds32(smem, OFF2_AL + r0 + wb);
                al[1] = lds32(smem, OFF2_AL + r8 + wb);
                al[2] = lds32(smem, OFF2_AL + r0 + wb + 16);
                al[3] = lds32(smem, OFF2_AL + r8 + wb + 16);
#pragma unroll
                for (int ni = 0; ni < 8; ni++) {
                    mma16816(acc[mi][ni], ah, bh[ni]);
                    mma16816(acc[mi][ni], al, bh[ni]);
                    mma16816(acc[mi][ni], ah, bl[ni]);
                }
            }
        }
    }

#pragma unroll
    for (int mi = 0; mi < 4; mi++) {
#pragma unroll
        for (int rr = 0; rr < 2; rr++) {
            const int row = wrow + mi * 16 + g + rr * 8;
            const size_t rbase = (row0 + row) * H_;
#pragma unroll
            for (int ni = 0; ni < 8; ni++) {
                const int col = wcol + ni * 8 + c * 2;
                float z0 = lrelu(acc[mi][ni][rr * 2 + 0] + c0[col]);
                float z1 = lrelu(acc[mi][ni][rr * 2 + 1] + c0[col + 1]);
                split_store2(g_h2h, g_h2l, rbase + col, z0, z1);
            }
        }
    }
}

// ===========================================================================
// Stage 3 (HMMA): fk = h2 @ W3 + b3 fused with contraction over i-tile
// Grid (NTILES, B), 256 threads. Warp tile 64 rows x 32 cols. K=256.
// ===========================================================================
__global__ __launch_bounds__(256, 1)
void k_stage3(const float* __restrict__ x, const float* __restrict__ b3) {
    extern __shared__ char smem[];
    const int t = threadIdx.x, w = t >> 5, lane = t & 31;
    const int i0 = blockIdx.x * TI, b = blockIdx.y;

    float* sx   = (float*)(smem + OFF3_X);     // [128][4]
    float* sred = (float*)(smem + OFF3_RED);   // [8][4][8][3]

    if (t < TI) {
        const float* xp = x + ((size_t)b * N_ + i0 + t) * 3;
        sx[t * 4 + 0] = xp[0]; sx[t * 4 + 1] = xp[1]; sx[t * 4 + 2] = xp[2];
    }

    const int wrow = (w & 1) * 64;
    const int wcol = (w >> 1) * 32;
    const int g = lane >> 2;
    const int c = lane & 3;

    float acc[4][4][4];
#pragma unroll
    for (int mi = 0; mi < 4; mi++)
#pragma unroll
        for (int ni = 0; ni < 4; ni++)
#pragma unroll
            for (int e = 0; e < 4; e++) acc[mi][ni][e] = 0.f;

    const size_t row0 = (size_t)b * N_ + i0;

    for (int ch = 0; ch < 4; ch++) {
        const int k0 = ch * KC;
        __syncthreads();

        // A chunk (h2 hi/lo)
#pragma unroll
        for (int m = 0; m < 4; m++) {
            const int q = t + m * 256;
            const int row = q >> 3, seg = q & 7;
            const int dst = row * SW_BYTES + seg * 16;
            const size_t src = (row0 + row) * H_ + k0 + seg * 8;
            *(uint4*)(smem + OFF3_A  + dst) = *(const uint4*)(g_h2h + src);
            *(uint4*)(smem + OFF3_AL + dst) = *(const uint4*)(g_h2l + src);
        }
        // W3 chunk: 128 rows x 64
#pragma unroll
        for (int m = 0; m < 4; m++) {
            const int q = t + m * 256;
            const int row = q >> 3, seg = q & 7;
            const int dst = row * SW_BYTES + seg * 16;
            const size_t src = (size_t)row * H_ + k0 + seg * 8;
            *(uint4*)(smem + OFF3_WH + dst) = *(const uint4*)(g_W3h + src);
            *(uint4*)(smem + OFF3_WL + dst) = *(const uint4*)(g_W3l + src);
        }
        __syncthreads();

#pragma unroll
        for (int k16 = 0; k16 < 4; k16++) {
            const int wb = (k16 * 8 + c) * 4;
            uint32_t bh[4][2], bl[4][2];
#pragma unroll
            for (int ni = 0; ni < 4; ni++) {
                const int rb = (wcol + ni * 8 + g) * SW_BYTES;
                bh[ni][0] = lds32(smem, OFF3_WH + rb + wb);
                bh[ni][1] = lds32(smem, OFF3_WH + rb + wb + 16);
                bl[ni][0] = lds32(smem, OFF3_WL + rb + wb);
                bl[ni][1] = lds32(smem, OFF3_WL + rb + wb + 16);
            }
#pragma unroll
            for (int mi = 0; mi < 4; mi++) {
                const int r0 = (wrow + mi * 16 + g) * SW_BYTES;
                const int r8 = r0 + 8 * SW_BYTES;
                uint32_t ah[4], al[4];
                ah[0] = lds32(smem, OFF3_A  + r0 + wb);
                ah[1] = lds32(smem, OFF3_A  + r8 + wb);
                ah[2] = lds32(smem, OFF3_A  + r0 + wb + 16);
                ah[3] = lds32(smem, OFF3_A  + r8 + wb + 16);
                al[0] = lds32(smem, OFF3_AL + r0 + wb);
                al[1] = lds32(smem, OFF3_AL + r8 + wb);
                al[2] = lds32(smem, OFF3_AL + r0 + wb + 16);
                al[3] = lds32(smem, OFF3_AL + r8 + wb + 16);
#pragma unroll
                for (int ni = 0; ni < 4; ni++) {
                    mma16816(acc[mi][ni], ah, bh[ni]);
                    mma16816(acc[mi][ni], al, bh[ni]);
                    mma16816(acc[mi][ni], ah, bl[ni]);
                }
            }
        }
    }

    // contraction: po[ni*2+e][d] = sum_rows (fk + b3) * x[row][d]
    float b3c[8];
#pragma unroll
    for (int ni = 0; ni < 4; ni++)
#pragma unroll
        for (int e = 0; e < 2; e++)
            b3c[ni * 2 + e] = b3[wcol + ni * 8 + c * 2 + e];

    float po[8][3];
#pragma unroll
    for (int k = 0; k < 8; k++) { po[k][0] = 0.f; po[k][1] = 0.f; po[k][2] = 0.f; }

#pragma unroll
    for (int mi = 0; mi < 4; mi++) {
#pragma unroll
        for (int rr = 0; rr < 2; rr++) {
            const int row = wrow + mi * 16 + g + rr * 8;
            const float x0 = sx[row * 4 + 0];
            const float x1 = sx[row * 4 + 1];
            const float x2 = sx[row * 4 + 2];
#pragma unroll
            for (int ni = 0; ni < 4; ni++) {
#pragma unroll
                for (int e = 0; e < 2; e++) {
                    const float f = acc[mi][ni][rr * 2 + e] + b3c[ni * 2 + e];
                    po[ni * 2 + e][0] = fmaf(f, x0, po[ni * 2 + e][0]);
                    po[ni * 2 + e][1] = fmaf(f, x1, po[ni * 2 + e][1]);
                    po[ni * 2 + e][2] = fmaf(f, x2, po[ni * 2 + e][2]);
                }
            }
        }
    }
    // reduce over g (stride-4 lanes)
#pragma unroll
    for (int k = 0; k < 8; k++)
#pragma unroll
        for (int d = 0; d < 3; d++) {
            po[k][d] += __shfl_down_sync(0xffffffffu, po[k][d], 16);
            po[k][d] += __shfl_down_sync(0xffffffffu, po[k][d], 8);
            po[k][d] += __shfl_down_sync(0xffffffffu, po[k][d], 4);
        }
    if (lane < 4) {
#pragma unroll
        for (int k = 0; k < 8; k++)
#pragma unroll
            for (int d = 0; d < 3; d++)
                sred[((w * 4 + lane) * 8 + k) * 3 + d] = po[k][d];
    }
    __syncthreads();

    if (t < KOUT_) {
        const int o = t;
        const int w0 = (o >> 5) * 2;          // col-group's two row-half warps
        const int cc = (o & 7) >> 1;
        const int kk = ((o >> 3) & 3) * 2 + (o & 1);
        float s[3];
#pragma unroll
        for (int d = 0; d < 3; d++)
            s[d] = sred[(((w0)     * 4 + cc) * 8 + kk) * 3 + d]
                 + sred[(((w0 + 1) * 4 + cc) * 8 + kk) * 3 + d];
        const size_t base = (((size_t)b * NTILES + blockIdx.x) * KOUT_ + o) * 3;
        g_part[base + 0] = s[0]; g_part[base + 1] = s[1]; g_part[base + 2] = s[2];
    }
}

// ===========================================================================
// Stage 4: reduce tiles
// ===========================================================================
__global__ void k_reduce(float* __restrict__ out) {
    int t = blockIdx.x * blockDim.x + threadIdx.x;
    if (t >= B_ * KOUT_ * 3) return;
    int b = t / (KOUT_ * 3), rem = t % (KOUT_ * 3);
    float s = 0.f;
#pragma unroll
    for (int tile = 0; tile < NTILES; tile++)
        s += g_part[((size_t)b * NTILES + tile) * KOUT_ * 3 + rem];
    out[t] = s * (1.0f / N_);
}

// ===========================================================================
extern "C" void kernel_launch(void* const* d_in, const int* in_sizes, int n_in,
                              void* d_out, int out_size) {
    const float* x     = (const float*)d_in[0];
    const float* u     = (const float*)d_in[1];
    const float* basis = (const float*)d_in[2];
    const float* W1    = (const float*)d_in[3];
    const float* b1    = (const float*)d_in[4];
    const float* W2    = (const float*)d_in[5];
    const float* b2    = (const float*)d_in[6];
    const float* W3    = (const float*)d_in[7];
    const float* b3    = (const float*)d_in[8];
    float* out = (float*)d_out;

    cudaFuncSetAttribute(k_stage1, cudaFuncAttributeMaxDynamicSharedMemorySize, SMEM_SZ1);
    cudaFuncSetAttribute(k_stage2, cudaFuncAttributeMaxDynamicSharedMemorySize, SMEM_SZ2);
    cudaFuncSetAttribute(k_stage3, cudaFuncAttributeMaxDynamicSharedMemorySize, SMEM_SZ3);

    __nv_bfloat16 *dWh, *dWl, *dW2h, *dW2l, *dW3h, *dW3l;
    cudaGetSymbolAddress((void**)&dWh,  g_Wh);
    cudaGetSymbolAddress((void**)&dWl,  g_Wl);
    cudaGetSymbolAddress((void**)&dW2h, g_W2h);
    cudaGetSymbolAddress((void**)&dW2l, g_W2l);
    cudaGetSymbolAddress((void**)&dW3h, g_W3h);
    cudaGetSymbolAddress((void**)&dW3l, g_W3l);

    k_prep_t<<<dim3(N_ / 32, H_ / 32), dim3(32, 8)>>>(W1 + 7 * H_, dWh, dWl, N_, H_);
    k_prep_t<<<dim3(H_ / 32, H_ / 32), dim3(32, 8)>>>(W2, dW2h, dW2l, H_, H_);
    k_prep_t<<<dim3(H_ / 32, KOUT_ / 32), dim3(32, 8)>>>(W3, dW3h, dW3l, H_, KOUT_);

    k_stage1<<<dim3(NTILES, B_), 256, SMEM_SZ1>>>(x, u, basis, W1, b1);
    k_stage2<<<(B_ * N_) / TI, 256, SMEM_SZ2>>>(b2);
    k_stage3<<<dim3(NTILES, B_), 256, SMEM_SZ3>>>(x, b3);
    k_reduce<<<(B_ * KOUT_ * 3 + 255) / 256, 256>>>(out);
}